// round 10
// baseline (speedup 1.0000x reference)
#include <cuda_runtime.h>
#include <cuda_bf16.h>
#include <cstdint>
#include <math.h>

#define S_LEN 4096
#define DM    1024
#define NH    16
#define HD    64
#define WIN   64

// ---------------- device scratch (no allocations allowed) ----------------
__device__ float g_q  [S_LEN * DM];
__device__ float g_k  [S_LEN * DM];
__device__ float g_v  [S_LEN * DM];
__device__ float g_xr [S_LEN * DM];      // tf32-rounded x
__device__ float g_wr [4 * DM * DM];     // tf32-rounded Wq,Wk,Wv,Wo
__device__ float g_aor[S_LEN * DM];      // tf32-rounded attention output

// ---------------- PTX helpers ----------------
__device__ __forceinline__ uint32_t smem_u32(const void* p) {
    uint32_t a;
    asm("{ .reg .u64 t; cvta.to.shared.u64 t, %1; cvt.u32.u64 %0, t; }" : "=r"(a) : "l"(p));
    return a;
}
#define CP16(dst, src) \
    asm volatile("cp.async.cg.shared.global [%0], [%1], 16;" :: "r"((uint32_t)(dst)), "l"(src) : "memory")
#define CP_COMMIT() asm volatile("cp.async.commit_group;" ::: "memory")
#define CP_WAIT2()  asm volatile("cp.async.wait_group 2;" ::: "memory")

#define LDSM4(r, addr) \
    asm volatile("ldmatrix.sync.aligned.m8n8.x4.shared.b16 {%0,%1,%2,%3}, [%4];" \
        : "=r"((r)[0]), "=r"((r)[1]), "=r"((r)[2]), "=r"((r)[3]) : "r"(addr))

#define MMA_TF32(d, a, b0v, b1v) \
    asm volatile("mma.sync.aligned.m16n8k8.row.col.f32.tf32.tf32.f32 " \
        "{%0,%1,%2,%3}, {%4,%5,%6,%7}, {%8,%9}, {%0,%1,%2,%3};" \
        : "+f"((d)[0]), "+f"((d)[1]), "+f"((d)[2]), "+f"((d)[3]) \
        : "r"((a)[0]), "r"((a)[1]), "r"((a)[2]), "r"((a)[3]), "r"(b0v), "r"(b1v))

__device__ __forceinline__ float tf32_rna(float x) {
    uint32_t t;
    asm("cvt.rna.tf32.f32 %0, %1;" : "=r"(t) : "f"(x));
    return __uint_as_float(t);
}

// ---------------- merged tf32 pre-round kernel ----------------
__global__ void round_all(const float* __restrict__ x,
                          const float* __restrict__ Wq, const float* __restrict__ Wk,
                          const float* __restrict__ Wv, const float* __restrict__ Wo,
                          float* __restrict__ xr, float* __restrict__ wr) {
    const int y = blockIdx.y;
    const float* src;
    float* dst;
    if (y < 4) {
        src = x  + (size_t)y * (S_LEN * DM / 4);
        dst = xr + (size_t)y * (S_LEN * DM / 4);
    } else {
        const float* W = y == 4 ? Wq : (y == 5 ? Wk : (y == 6 ? Wv : Wo));
        src = W;
        dst = wr + (size_t)(y - 4) * DM * DM;
    }
    int i = blockIdx.x * blockDim.x + threadIdx.x;
    float4 f = ((const float4*)src)[i];
    ((float4*)dst)[i] = make_float4(tf32_rna(f.x), tf32_rna(f.y), tf32_rna(f.z), tf32_rna(f.w));
}

// ---------------------------------------------------------------------------
// tf32 GEMM v6: CTA 128x128, BK=16, A|B interleaved 128B lines, 4-stage
// cp.async (16KB/stage, 64KB total) with prefetch depth 3, 4 warps (2x2,
// 64x64), 3 CTAs/SM.  Line r = [A row r: 16 floats | B row r: 16 floats],
// 16B-chunk swizzle c ^ (r&7) over the 8-chunk line (A chunks 0-3, B 4-7).
// ---------------------------------------------------------------------------
#define STAGE_B 16384                 // 128 lines x 128B
#define NSTAGE  4
#define GEMM_SMEM (NSTAGE * STAGE_B)  // 65536 -> 3 CTAs/SM

__global__ __launch_bounds__(128, 3) void gemm_tf32(
    const float* __restrict__ A, const float* __restrict__ Wr,
    int w_off, float* __restrict__ C0, float* __restrict__ C1, float* __restrict__ C2)
{
    extern __shared__ char sm[];
    const int z = blockIdx.z;
    const float* B = Wr + (size_t)(w_off + z) * DM * DM;
    float* C = z == 0 ? C0 : (z == 1 ? C1 : C2);

    const uint32_t smem_base = smem_u32(sm);
    const int tid  = threadIdx.x;
    const int lane = tid & 31;
    const int wid  = tid >> 5;
    const int wm   = wid & 1;
    const int wn   = wid >> 1;
    const int m0 = blockIdx.y * 128;
    const int n0 = blockIdx.x * 128;

    // loader: 8 chunks/thread/stage; c = tid&7 fixed per thread (A if c<4)
    uint32_t swo[8];
    const float* gsrc[8];
#pragma unroll
    for (int jj = 0; jj < 8; jj++) {
        int qq = tid + 128 * jj;
        int r = qq >> 3, c = qq & 7;
        swo[jj] = (uint32_t)(r * 128 + ((c ^ (r & 7)) << 4));
        gsrc[jj] = (c < 4) ? (A + (size_t)(m0 + r) * DM + c * 4)
                           : (B + (size_t)(n0 + r) * DM + (c - 4) * 4);
    }

    const int lm   = lane >> 3;
    const int lrow = lane & 7;
    const int cSel = lm >> 1;
    uint32_t aOff[4]; int aXor[4];
#pragma unroll
    for (int mi = 0; mi < 4; mi++) {
        int ar = wm * 64 + mi * 16 + (lm & 1) * 8 + lrow;
        aOff[mi] = (uint32_t)(ar * 128); aXor[mi] = ar & 7;
    }
    uint32_t bOff[4]; int bXor[4];
#pragma unroll
    for (int pb = 0; pb < 4; pb++) {
        int br = wn * 64 + pb * 16 + (lm & 1) * 8 + lrow;
        bOff[pb] = (uint32_t)(br * 128); bXor[pb] = br & 7;
    }

    float acc[4][8][4];
#pragma unroll
    for (int mi = 0; mi < 4; mi++)
#pragma unroll
        for (int nb = 0; nb < 8; nb++)
#pragma unroll
            for (int e = 0; e < 4; e++) acc[mi][nb][e] = 0.0f;

    const int ITERS = DM / 16;   // 64

    auto issue = [&](int t) {
        const uint32_t sb = smem_base + (uint32_t)(t & 3) * STAGE_B;
        const uint32_t kt = (uint32_t)(t * 16);
#pragma unroll
        for (int jj = 0; jj < 8; jj++)
            CP16(sb + swo[jj], (const char*)(gsrc[jj] + kt));
        CP_COMMIT();
    };

    issue(0); issue(1); issue(2);

    for (int t = 0; t < ITERS; t++) {
        CP_WAIT2();          // group t complete (<=2 younger pending)
        __syncthreads();     // data visible; slot (t+3)&3 free (compute(t-1) done)
        if (t + 3 < ITERS) issue(t + 3);

        const uint32_t sb = smem_base + (uint32_t)(t & 3) * STAGE_B;

#pragma unroll
        for (int s = 0; s < 2; s++) {            // two k8 steps in BK=16
            uint32_t fA[4][4];
#pragma unroll
            for (int mi = 0; mi < 4; mi++)
                LDSM4(fA[mi], sb + aOff[mi] + (uint32_t)((((2 * s) + cSel) ^ aXor[mi]) << 4));
            uint32_t fB[8][2];
#pragma unroll
            for (int pb = 0; pb < 4; pb++) {
                uint32_t bt[4];
                LDSM4(bt, sb + bOff[pb] + (uint32_t)(((4 + (2 * s) + cSel) ^ bXor[pb]) << 4));
                fB[2 * pb][0] = bt[0]; fB[2 * pb][1] = bt[2];
                fB[2 * pb + 1][0] = bt[1]; fB[2 * pb + 1][1] = bt[3];
            }
#pragma unroll
            for (int mi = 0; mi < 4; mi++)
#pragma unroll
                for (int nb = 0; nb < 8; nb++)
                    MMA_TF32(acc[mi][nb], fA[mi], fB[nb][0], fB[nb][1]);
        }
    }

    const int crow0 = m0 + wm * 64 + (lane >> 2);
    const int ccol0 = n0 + wn * 64 + (lane & 3) * 2;
#pragma unroll
    for (int mi = 0; mi < 4; mi++) {
#pragma unroll
        for (int nb = 0; nb < 8; nb++) {
            const int row = crow0 + mi * 16;
            const int col = ccol0 + nb * 8;
            *(float2*)&C[(size_t)row * DM + col]       = make_float2(acc[mi][nb][0], acc[mi][nb][1]);
            *(float2*)&C[(size_t)(row + 8) * DM + col] = make_float2(acc[mi][nb][2], acc[mi][nb][3]);
        }
    }
}

// ---------------------------------------------------------------------------
// Sliding-window attention v4 (unchanged — 76.7us).
// ---------------------------------------------------------------------------
#define ATT_PAD 68
#define ATT_ROWS 127
#define PS_STR 67
#define ATT_SMEM_BYTES (2 * ATT_ROWS * ATT_PAD * 4)   // 69088

__global__ __launch_bounds__(128, 3) void swattn(
    const float* __restrict__ q, const float* __restrict__ k,
    const float* __restrict__ v, float* __restrict__ o)
{
    extern __shared__ float smf[];
    float* Ks = smf;
    float* Vs = smf + ATT_ROWS * ATT_PAD;
    float* Ps = smf;

    const int qstart  = blockIdx.x * 64;
    const int h       = blockIdx.y;
    const int korigin = qstart - (WIN - 1);
    const int hcol    = h * HD;

    const int tid = threadIdx.x;
    const int qg  = tid >> 2;
    const int hv  = tid & 3;
    const int e   = hv & 1;

    int ch[4];
#pragma unroll
    for (int j = 0; j < 4; j++)
        ch[j] = (hv & 1) + ((hv >> 1) << 2) + ((j & 1) << 1) + ((j >> 1) << 3);

    for (int i = tid; i < ATT_ROWS * 16; i += 128) {
        const int r  = i >> 4;
        const int c4 = (i & 15) << 2;
        const int g  = korigin + r;
        float4 kk = make_float4(0.f, 0.f, 0.f, 0.f);
        float4 vv = kk;
        if (g >= 0) {
            kk = *(const float4*)&k[(size_t)g * DM + hcol + c4];
            vv = *(const float4*)&v[(size_t)g * DM + hcol + c4];
        }
        *(float4*)&Ks[r * ATT_PAD + c4] = kk;
        *(float4*)&Vs[r * ATT_PAD + c4] = vv;
    }

    float qreg[2][16];
#pragma unroll
    for (int eq = 0; eq < 2; eq++) {
        const float* qrow = &q[(size_t)(qstart + 2 * qg + eq) * DM + hcol];
#pragma unroll
        for (int j = 0; j < 4; j++) {
            float4 t4 = *(const float4*)&qrow[4 * ch[j]];
            qreg[eq][4*j+0] = t4.x * 0.125f;
            qreg[eq][4*j+1] = t4.y * 0.125f;
            qreg[eq][4*j+2] = t4.z * 0.125f;
            qreg[eq][4*j+3] = t4.w * 0.125f;
        }
    }
    __syncthreads();

    float s[65];
#pragma unroll
    for (int i = 0; i <= 64; i++) {
        const int r = 2 * qg + i;
        const float* kr = &Ks[r * ATT_PAD];
        float u0 = 0.f, u1 = 0.f, w0 = 0.f, w1 = 0.f;
#pragma unroll
        for (int j = 0; j < 4; j++) {
            float4 kk = *(const float4*)&kr[4 * ch[j]];
            if (j & 1) {
                u1 = fmaf(qreg[0][4*j+0], kk.x, u1); u1 = fmaf(qreg[0][4*j+1], kk.y, u1);
                u1 = fmaf(qreg[0][4*j+2], kk.z, u1); u1 = fmaf(qreg[0][4*j+3], kk.w, u1);
                w1 = fmaf(qreg[1][4*j+0], kk.x, w1); w1 = fmaf(qreg[1][4*j+1], kk.y, w1);
                w1 = fmaf(qreg[1][4*j+2], kk.z, w1); w1 = fmaf(qreg[1][4*j+3], kk.w, w1);
            } else {
                u0 = fmaf(qreg[0][4*j+0], kk.x, u0); u0 = fmaf(qreg[0][4*j+1], kk.y, u0);
                u0 = fmaf(qreg[0][4*j+2], kk.z, u0); u0 = fmaf(qreg[0][4*j+3], kk.w, u0);
                w0 = fmaf(qreg[1][4*j+0], kk.x, w0); w0 = fmaf(qreg[1][4*j+1], kk.y, w0);
                w0 = fmaf(qreg[1][4*j+2], kk.z, w0); w0 = fmaf(qreg[1][4*j+3], kk.w, w0);
            }
        }
        float u = u0 + u1;
        float wv = w0 + w1;
        u  += __shfl_xor_sync(0xffffffffu, u, 1);
        u  += __shfl_xor_sync(0xffffffffu, u, 2);
        wv += __shfl_xor_sync(0xffffffffu, wv, 1);
        wv += __shfl_xor_sync(0xffffffffu, wv, 2);
        const float sc = e ? wv : u;
        const bool valid = (korigin + r >= 0) && (e ? (i >= 1) : (i <= 63));
        s[i] = valid ? sc : -INFINITY;
    }

    float mx = -INFINITY;
#pragma unroll
    for (int i = 0; i <= 64; i++) mx = fmaxf(mx, s[i]);
    float sum = 0.0f;
#pragma unroll
    for (int i = 0; i <= 64; i++) { s[i] = __expf(s[i] - mx); sum += s[i]; }
    const float inv = 1.0f / sum;
#pragma unroll
    for (int i = 0; i <= 64; i++) s[i] *= inv;

    __syncthreads();

    if (hv < 2) {
        const int base = (2 * qg + e) * PS_STR;
#pragma unroll
        for (int i = 0; i <= 64; i++) {
            const int w = i - e;
            if (w >= 0 && w <= 63) Ps[base + w] = s[i];
        }
    }
    __syncthreads();

    float accv[2][16];
#pragma unroll
    for (int d = 0; d < 16; d++) { accv[0][d] = 0.f; accv[1][d] = 0.f; }

#pragma unroll 4
    for (int i = 0; i <= 64; i++) {
        const int r = 2 * qg + i;
        const float pw0 = (i <= 63) ? Ps[(2 * qg) * PS_STR + i]         : 0.f;
        const float pw1 = (i >= 1)  ? Ps[(2 * qg + 1) * PS_STR + i - 1] : 0.f;
        const float* vr = &Vs[r * ATT_PAD];
#pragma unroll
        for (int j = 0; j < 4; j++) {
            float4 vv = *(const float4*)&vr[4 * ch[j]];
            accv[0][4*j+0] = fmaf(pw0, vv.x, accv[0][4*j+0]);
            accv[0][4*j+1] = fmaf(pw0, vv.y, accv[0][4*j+1]);
            accv[0][4*j+2] = fmaf(pw0, vv.z, accv[0][4*j+2]);
            accv[0][4*j+3] = fmaf(pw0, vv.w, accv[0][4*j+3]);
            accv[1][4*j+0] = fmaf(pw1, vv.x, accv[1][4*j+0]);
            accv[1][4*j+1] = fmaf(pw1, vv.y, accv[1][4*j+1]);
            accv[1][4*j+2] = fmaf(pw1, vv.z, accv[1][4*j+2]);
            accv[1][4*j+3] = fmaf(pw1, vv.w, accv[1][4*j+3]);
        }
    }

#pragma unroll
    for (int eq = 0; eq < 2; eq++) {
        float* orow = &o[(size_t)(qstart + 2 * qg + eq) * DM + hcol];
#pragma unroll
        for (int j = 0; j < 4; j++)
            *(float4*)&orow[4 * ch[j]] = make_float4(
                tf32_rna(accv[eq][4*j+0]), tf32_rna(accv[eq][4*j+1]),
                tf32_rna(accv[eq][4*j+2]), tf32_rna(accv[eq][4*j+3]));
    }
}

// ---------------- launch ----------------
extern "C" void kernel_launch(void* const* d_in, const int* in_sizes, int n_in,
                              void* d_out, int out_size)
{
    const float* x  = (const float*)d_in[0];
    const float* Wq = (const float*)d_in[1];
    const float* Wk = (const float*)d_in[2];
    const float* Wv = (const float*)d_in[3];
    const float* Wo = (const float*)d_in[4];
    float* out = (float*)d_out;

    float *qp, *kp, *vp, *xr, *wr, *aor;
    cudaGetSymbolAddress((void**)&qp,  g_q);
    cudaGetSymbolAddress((void**)&kp,  g_k);
    cudaGetSymbolAddress((void**)&vp,  g_v);
    cudaGetSymbolAddress((void**)&xr,  g_xr);
    cudaGetSymbolAddress((void**)&wr,  g_wr);
    cudaGetSymbolAddress((void**)&aor, g_aor);

    cudaFuncSetAttribute(gemm_tf32, cudaFuncAttributeMaxDynamicSharedMemorySize, GEMM_SMEM);
    cudaFuncSetAttribute(swattn,    cudaFuncAttributeMaxDynamicSharedMemorySize, ATT_SMEM_BYTES);

    // 1. pre-round x and all W to tf32 (single launch)
    round_all<<<dim3(S_LEN * DM / 4 / 4 / 256, 8), 256>>>(x, Wq, Wk, Wv, Wo, xr, wr);

    // 2. QKV projections (fused via grid.z)
    gemm_tf32<<<dim3(DM / 128, S_LEN / 128, 3), 128, GEMM_SMEM>>>(xr, wr, 0, qp, kp, vp);

    // 3. sliding-window attention
    swattn<<<dim3(S_LEN / 64, NH), 128, ATT_SMEM_BYTES>>>(qp, kp, vp, aor);

    // 4. output projection
    gemm_tf32<<<dim3(DM / 128, S_LEN / 128, 1), 128, GEMM_SMEM>>>(aor, wr, 3, out, out, out);
}

// round 11
// speedup vs baseline: 1.1673x; 1.1673x over previous
#include <cuda_runtime.h>
#include <cuda_bf16.h>
#include <cstdint>
#include <math.h>

#define S_LEN 4096
#define DM    1024
#define NH    16
#define HD    64
#define WIN   64

// ---------------- device scratch (no allocations allowed) ----------------
__device__ float g_q  [S_LEN * DM];
__device__ float g_k  [S_LEN * DM];
__device__ float g_v  [S_LEN * DM];
__device__ float g_xr [S_LEN * DM];      // tf32-rounded x
__device__ float g_wr [4 * DM * DM];     // tf32-rounded Wq,Wk,Wv,Wo
__device__ float g_aor[S_LEN * DM];      // tf32-rounded attention output

// ---------------- PTX helpers ----------------
__device__ __forceinline__ uint32_t smem_u32(const void* p) {
    uint32_t a;
    asm("{ .reg .u64 t; cvta.to.shared.u64 t, %1; cvt.u32.u64 %0, t; }" : "=r"(a) : "l"(p));
    return a;
}
#define CP16(dst, src) \
    asm volatile("cp.async.cg.shared.global [%0], [%1], 16;" :: "r"((uint32_t)(dst)), "l"(src) : "memory")
#define CP_COMMIT() asm volatile("cp.async.commit_group;" ::: "memory")
#define CP_WAIT1()  asm volatile("cp.async.wait_group 1;" ::: "memory")

#define LDSM4(r, addr) \
    asm volatile("ldmatrix.sync.aligned.m8n8.x4.shared.b16 {%0,%1,%2,%3}, [%4];" \
        : "=r"((r)[0]), "=r"((r)[1]), "=r"((r)[2]), "=r"((r)[3]) : "r"(addr))

#define MMA_TF32(d, a, b0v, b1v) \
    asm volatile("mma.sync.aligned.m16n8k8.row.col.f32.tf32.tf32.f32 " \
        "{%0,%1,%2,%3}, {%4,%5,%6,%7}, {%8,%9}, {%0,%1,%2,%3};" \
        : "+f"((d)[0]), "+f"((d)[1]), "+f"((d)[2]), "+f"((d)[3]) \
        : "r"((a)[0]), "r"((a)[1]), "r"((a)[2]), "r"((a)[3]), "r"(b0v), "r"(b1v))

__device__ __forceinline__ float tf32_rna(float x) {
    uint32_t t;
    asm("cvt.rna.tf32.f32 %0, %1;" : "=r"(t) : "f"(x));
    return __uint_as_float(t);
}

// ---------------- merged tf32 pre-round kernel ----------------
__global__ void round_all(const float* __restrict__ x,
                          const float* __restrict__ Wq, const float* __restrict__ Wk,
                          const float* __restrict__ Wv, const float* __restrict__ Wo,
                          float* __restrict__ xr, float* __restrict__ wr) {
    const int y = blockIdx.y;
    const float* src;
    float* dst;
    if (y < 4) {
        src = x  + (size_t)y * (S_LEN * DM / 4);
        dst = xr + (size_t)y * (S_LEN * DM / 4);
    } else {
        const float* W = y == 4 ? Wq : (y == 5 ? Wk : (y == 6 ? Wv : Wo));
        src = W;
        dst = wr + (size_t)(y - 4) * DM * DM;
    }
    int i = blockIdx.x * blockDim.x + threadIdx.x;
    float4 f = ((const float4*)src)[i];
    ((float4*)dst)[i] = make_float4(tf32_rna(f.x), tf32_rna(f.y), tf32_rna(f.z), tf32_rna(f.w));
}

// ---------------------------------------------------------------------------
// tf32 GEMM v7: R7-proven inner loop (CTA 128x128, BK=32, 3-stage cp.async,
// 4 warps 2x2 / 64x64, 2 CTAs/SM) + in-kernel z-loop: one CTA computes the
// SAME output tile for nz consecutive weight matrices (grid=256 -> no
// partial-wave tail on the QKV launch).
// ---------------------------------------------------------------------------
#define TILE_B  16384
#define STAGE_B (2 * TILE_B)
#define NSTAGE  3
#define GEMM_SMEM (NSTAGE * STAGE_B)  // 98304 -> 2 CTAs/SM

__global__ __launch_bounds__(128, 2) void gemm_tf32(
    const float* __restrict__ A, const float* __restrict__ Wr,
    int w_off, int nz,
    float* __restrict__ C0, float* __restrict__ C1, float* __restrict__ C2)
{
    extern __shared__ char sm[];
    const uint32_t smem_base = smem_u32(sm);
    const int tid  = threadIdx.x;
    const int lane = tid & 31;
    const int wid  = tid >> 5;
    const int wm   = wid & 1;
    const int wn   = wid >> 1;
    const int m0 = blockIdx.y * 128;
    const int n0 = blockIdx.x * 128;

    // loader mapping (offsets; B base added per z)
    uint32_t swo[8], gA[8], gB[8];
#pragma unroll
    for (int jj = 0; jj < 8; jj++) {
        int qq = tid + 128 * jj;
        int r = qq >> 3, c = qq & 7;
        swo[jj] = (uint32_t)(r * 128 + ((c ^ (r & 7)) << 4));
        gA[jj] = (uint32_t)((m0 + r) * DM + c * 4);
        gB[jj] = (uint32_t)((n0 + r) * DM + c * 4);
    }

    const int lm   = lane >> 3;
    const int lrow = lane & 7;
    const int cSel = lm >> 1;
    uint32_t aOff[4]; int aXor[4];
#pragma unroll
    for (int mi = 0; mi < 4; mi++) {
        int ar = wm * 64 + mi * 16 + (lm & 1) * 8 + lrow;
        aOff[mi] = (uint32_t)(ar * 128); aXor[mi] = ar & 7;
    }
    uint32_t bOff[4]; int bXor[4];
#pragma unroll
    for (int pb = 0; pb < 4; pb++) {
        int br = wn * 64 + pb * 16 + (lm & 1) * 8 + lrow;
        bOff[pb] = (uint32_t)(br * 128); bXor[pb] = br & 7;
    }

    const int ITERS = DM / 32;   // 32

    for (int zi = 0; zi < nz; zi++) {
        const float* B = Wr + (size_t)(w_off + zi) * DM * DM;
        float* C = zi == 0 ? C0 : (zi == 1 ? C1 : C2);

        float acc[4][8][4];
#pragma unroll
        for (int mi = 0; mi < 4; mi++)
#pragma unroll
            for (int nb = 0; nb < 8; nb++)
#pragma unroll
                for (int e = 0; e < 4; e++) acc[mi][nb][e] = 0.0f;

        auto issue = [&](int t) {
            const uint32_t sb = smem_base + (uint32_t)(t % NSTAGE) * STAGE_B;
            const uint32_t kt = (uint32_t)(t * 32);
#pragma unroll
            for (int jj = 0; jj < 8; jj++) {
                CP16(sb + swo[jj],          (const char*)A + (size_t)(gA[jj] + kt) * 4);
                CP16(sb + TILE_B + swo[jj], (const char*)B + (size_t)(gB[jj] + kt) * 4);
            }
            CP_COMMIT();
        };

        __syncthreads();    // segment barrier: no warp still reading prior-z smem
        issue(0); issue(1);

        for (int t = 0; t < ITERS; t++) {
            CP_WAIT1();
            __syncthreads();
            if (t + 2 < ITERS) issue(t + 2);

            const uint32_t sb = smem_base + (uint32_t)(t % NSTAGE) * STAGE_B;
            const uint32_t aBase = sb, bBase = sb + TILE_B;

#pragma unroll
            for (int s = 0; s < 4; s++) {
                uint32_t fA[4][4];
#pragma unroll
                for (int mi = 0; mi < 4; mi++)
                    LDSM4(fA[mi], aBase + aOff[mi] + (uint32_t)((((2 * s) + cSel) ^ aXor[mi]) << 4));
                uint32_t fB[8][2];
#pragma unroll
                for (int pb = 0; pb < 4; pb++) {
                    uint32_t bt[4];
                    LDSM4(bt, bBase + bOff[pb] + (uint32_t)((((2 * s) + cSel) ^ bXor[pb]) << 4));
                    fB[2 * pb][0] = bt[0]; fB[2 * pb][1] = bt[2];
                    fB[2 * pb + 1][0] = bt[1]; fB[2 * pb + 1][1] = bt[3];
                }
#pragma unroll
                for (int mi = 0; mi < 4; mi++)
#pragma unroll
                    for (int nb = 0; nb < 8; nb++)
                        MMA_TF32(acc[mi][nb], fA[mi], fB[nb][0], fB[nb][1]);
            }
        }

        const int crow0 = m0 + wm * 64 + (lane >> 2);
        const int ccol0 = n0 + wn * 64 + (lane & 3) * 2;
#pragma unroll
        for (int mi = 0; mi < 4; mi++) {
#pragma unroll
            for (int nb = 0; nb < 8; nb++) {
                const int row = crow0 + mi * 16;
                const int col = ccol0 + nb * 8;
                *(float2*)&C[(size_t)row * DM + col]       = make_float2(acc[mi][nb][0], acc[mi][nb][1]);
                *(float2*)&C[(size_t)(row + 8) * DM + col] = make_float2(acc[mi][nb][2], acc[mi][nb][3]);
            }
        }
    }
}

// ---------------------------------------------------------------------------
// Sliding-window attention v4 (unchanged — 76.7us).
// ---------------------------------------------------------------------------
#define ATT_PAD 68
#define ATT_ROWS 127
#define PS_STR 67
#define ATT_SMEM_BYTES (2 * ATT_ROWS * ATT_PAD * 4)   // 69088

__global__ __launch_bounds__(128, 3) void swattn(
    const float* __restrict__ q, const float* __restrict__ k,
    const float* __restrict__ v, float* __restrict__ o)
{
    extern __shared__ float smf[];
    float* Ks = smf;
    float* Vs = smf + ATT_ROWS * ATT_PAD;
    float* Ps = smf;

    const int qstart  = blockIdx.x * 64;
    const int h       = blockIdx.y;
    const int korigin = qstart - (WIN - 1);
    const int hcol    = h * HD;

    const int tid = threadIdx.x;
    const int qg  = tid >> 2;
    const int hv  = tid & 3;
    const int e   = hv & 1;

    int ch[4];
#pragma unroll
    for (int j = 0; j < 4; j++)
        ch[j] = (hv & 1) + ((hv >> 1) << 2) + ((j & 1) << 1) + ((j >> 1) << 3);

    for (int i = tid; i < ATT_ROWS * 16; i += 128) {
        const int r  = i >> 4;
        const int c4 = (i & 15) << 2;
        const int g  = korigin + r;
        float4 kk = make_float4(0.f, 0.f, 0.f, 0.f);
        float4 vv = kk;
        if (g >= 0) {
            kk = *(const float4*)&k[(size_t)g * DM + hcol + c4];
            vv = *(const float4*)&v[(size_t)g * DM + hcol + c4];
        }
        *(float4*)&Ks[r * ATT_PAD + c4] = kk;
        *(float4*)&Vs[r * ATT_PAD + c4] = vv;
    }

    float qreg[2][16];
#pragma unroll
    for (int eq = 0; eq < 2; eq++) {
        const float* qrow = &q[(size_t)(qstart + 2 * qg + eq) * DM + hcol];
#pragma unroll
        for (int j = 0; j < 4; j++) {
            float4 t4 = *(const float4*)&qrow[4 * ch[j]];
            qreg[eq][4*j+0] = t4.x * 0.125f;
            qreg[eq][4*j+1] = t4.y * 0.125f;
            qreg[eq][4*j+2] = t4.z * 0.125f;
            qreg[eq][4*j+3] = t4.w * 0.125f;
        }
    }
    __syncthreads();

    float s[65];
#pragma unroll
    for (int i = 0; i <= 64; i++) {
        const int r = 2 * qg + i;
        const float* kr = &Ks[r * ATT_PAD];
        float u0 = 0.f, u1 = 0.f, w0 = 0.f, w1 = 0.f;
#pragma unroll
        for (int j = 0; j < 4; j++) {
            float4 kk = *(const float4*)&kr[4 * ch[j]];
            if (j & 1) {
                u1 = fmaf(qreg[0][4*j+0], kk.x, u1); u1 = fmaf(qreg[0][4*j+1], kk.y, u1);
                u1 = fmaf(qreg[0][4*j+2], kk.z, u1); u1 = fmaf(qreg[0][4*j+3], kk.w, u1);
                w1 = fmaf(qreg[1][4*j+0], kk.x, w1); w1 = fmaf(qreg[1][4*j+1], kk.y, w1);
                w1 = fmaf(qreg[1][4*j+2], kk.z, w1); w1 = fmaf(qreg[1][4*j+3], kk.w, w1);
            } else {
                u0 = fmaf(qreg[0][4*j+0], kk.x, u0); u0 = fmaf(qreg[0][4*j+1], kk.y, u0);
                u0 = fmaf(qreg[0][4*j+2], kk.z, u0); u0 = fmaf(qreg[0][4*j+3], kk.w, u0);
                w0 = fmaf(qreg[1][4*j+0], kk.x, w0); w0 = fmaf(qreg[1][4*j+1], kk.y, w0);
                w0 = fmaf(qreg[1][4*j+2], kk.z, w0); w0 = fmaf(qreg[1][4*j+3], kk.w, w0);
            }
        }
        float u = u0 + u1;
        float wv = w0 + w1;
        u  += __shfl_xor_sync(0xffffffffu, u, 1);
        u  += __shfl_xor_sync(0xffffffffu, u, 2);
        wv += __shfl_xor_sync(0xffffffffu, wv, 1);
        wv += __shfl_xor_sync(0xffffffffu, wv, 2);
        const float sc = e ? wv : u;
        const bool valid = (korigin + r >= 0) && (e ? (i >= 1) : (i <= 63));
        s[i] = valid ? sc : -INFINITY;
    }

    float mx = -INFINITY;
#pragma unroll
    for (int i = 0; i <= 64; i++) mx = fmaxf(mx, s[i]);
    float sum = 0.0f;
#pragma unroll
    for (int i = 0; i <= 64; i++) { s[i] = __expf(s[i] - mx); sum += s[i]; }
    const float inv = 1.0f / sum;
#pragma unroll
    for (int i = 0; i <= 64; i++) s[i] *= inv;

    __syncthreads();

    if (hv < 2) {
        const int base = (2 * qg + e) * PS_STR;
#pragma unroll
        for (int i = 0; i <= 64; i++) {
            const int w = i - e;
            if (w >= 0 && w <= 63) Ps[base + w] = s[i];
        }
    }
    __syncthreads();

    float accv[2][16];
#pragma unroll
    for (int d = 0; d < 16; d++) { accv[0][d] = 0.f; accv[1][d] = 0.f; }

#pragma unroll 4
    for (int i = 0; i <= 64; i++) {
        const int r = 2 * qg + i;
        const float pw0 = (i <= 63) ? Ps[(2 * qg) * PS_STR + i]         : 0.f;
        const float pw1 = (i >= 1)  ? Ps[(2 * qg + 1) * PS_STR + i - 1] : 0.f;
        const float* vr = &Vs[r * ATT_PAD];
#pragma unroll
        for (int j = 0; j < 4; j++) {
            float4 vv = *(const float4*)&vr[4 * ch[j]];
            accv[0][4*j+0] = fmaf(pw0, vv.x, accv[0][4*j+0]);
            accv[0][4*j+1] = fmaf(pw0, vv.y, accv[0][4*j+1]);
            accv[0][4*j+2] = fmaf(pw0, vv.z, accv[0][4*j+2]);
            accv[0][4*j+3] = fmaf(pw0, vv.w, accv[0][4*j+3]);
            accv[1][4*j+0] = fmaf(pw1, vv.x, accv[1][4*j+0]);
            accv[1][4*j+1] = fmaf(pw1, vv.y, accv[1][4*j+1]);
            accv[1][4*j+2] = fmaf(pw1, vv.z, accv[1][4*j+2]);
            accv[1][4*j+3] = fmaf(pw1, vv.w, accv[1][4*j+3]);
        }
    }

#pragma unroll
    for (int eq = 0; eq < 2; eq++) {
        float* orow = &o[(size_t)(qstart + 2 * qg + eq) * DM + hcol];
#pragma unroll
        for (int j = 0; j < 4; j++)
            *(float4*)&orow[4 * ch[j]] = make_float4(
                tf32_rna(accv[eq][4*j+0]), tf32_rna(accv[eq][4*j+1]),
                tf32_rna(accv[eq][4*j+2]), tf32_rna(accv[eq][4*j+3]));
    }
}

// ---------------- launch ----------------
extern "C" void kernel_launch(void* const* d_in, const int* in_sizes, int n_in,
                              void* d_out, int out_size)
{
    const float* x  = (const float*)d_in[0];
    const float* Wq = (const float*)d_in[1];
    const float* Wk = (const float*)d_in[2];
    const float* Wv = (const float*)d_in[3];
    const float* Wo = (const float*)d_in[4];
    float* out = (float*)d_out;

    float *qp, *kp, *vp, *xr, *wr, *aor;
    cudaGetSymbolAddress((void**)&qp,  g_q);
    cudaGetSymbolAddress((void**)&kp,  g_k);
    cudaGetSymbolAddress((void**)&vp,  g_v);
    cudaGetSymbolAddress((void**)&xr,  g_xr);
    cudaGetSymbolAddress((void**)&wr,  g_wr);
    cudaGetSymbolAddress((void**)&aor, g_aor);

    cudaFuncSetAttribute(gemm_tf32, cudaFuncAttributeMaxDynamicSharedMemorySize, GEMM_SMEM);
    cudaFuncSetAttribute(swattn,    cudaFuncAttributeMaxDynamicSharedMemorySize, ATT_SMEM_BYTES);

    // 1. pre-round x and all W to tf32 (single launch)
    round_all<<<dim3(S_LEN * DM / 4 / 4 / 256, 8), 256>>>(x, Wq, Wk, Wv, Wo, xr, wr);

    // 2. QKV projections: 256 CTAs, 3 weight matrices per CTA (no wave tail)
    gemm_tf32<<<dim3(DM / 128, S_LEN / 128), 128, GEMM_SMEM>>>(xr, wr, 0, 3, qp, kp, vp);

    // 3. sliding-window attention
    swattn<<<dim3(S_LEN / 64, NH), 128, ATT_SMEM_BYTES>>>(qp, kp, vp, aor);

    // 4. output projection
    gemm_tf32<<<dim3(DM / 128, S_LEN / 128), 128, GEMM_SMEM>>>(aor, wr, 3, 1, out, out, out);
}